// round 7
// baseline (speedup 1.0000x reference)
#include <cuda_runtime.h>

#define BATCH 128
#define CH 256
#define HW 3136          // 56*56
#define PFD 8            // per-filter dim
#define KDIM 2048        // CH*PFD
#define JH 256           // final hidden
#define NCLS 1000
#define KSPLIT 16        // k-splits for gemm2
#define JTILES 8         // 256/32

// Scratch (allocation-free rule: __device__ globals)
__device__ float g_concat[BATCH * KDIM];            // 1 MB
__device__ float g_hpart[KSPLIT * BATCH * JH];      // 2 MB, deterministic split-K partials
__device__ float g_h[BATCH * JH];                   // 128 KB, reduced+bias+relu hidden

// ---------------------------------------------------------------------------
// Kernel 1: global average pool fused with per-channel Linear(1->8)+ReLU.
// One warp per (b,c) pair; 8 front-batched float4 LDGs per chunk (MLP=8).
// ---------------------------------------------------------------------------
__global__ void __launch_bounds__(512) pool_kernel(const float* __restrict__ x,
                                                   const float* __restrict__ W1,
                                                   const float* __restrict__ b1) {
    int warp = threadIdx.x >> 5;
    int lane = threadIdx.x & 31;
    int pair = blockIdx.x * 16 + warp;       // pair = b*CH + c, in [0, 32768)
    const float4* xv = (const float4*)(x + (long)pair * HW);

    float s0 = 0.f, s1 = 0.f, s2 = 0.f, s3 = 0.f;
    // 784 float4 per pair = 3 chunks of 8x32 + tail of 16
    #pragma unroll
    for (int c = 0; c < 3; c++) {
        float4 v[8];
        #pragma unroll
        for (int u = 0; u < 8; u++)
            v[u] = xv[lane + 32 * u + 256 * c];
        #pragma unroll
        for (int u = 0; u < 8; u += 4) {
            s0 += v[u].x + v[u].y;         s1 += v[u].z + v[u].w;
            s2 += v[u+1].x + v[u+1].y;     s3 += v[u+1].z + v[u+1].w;
            s0 += v[u+2].x + v[u+2].y;     s1 += v[u+2].z + v[u+2].w;
            s2 += v[u+3].x + v[u+3].y;     s3 += v[u+3].z + v[u+3].w;
        }
    }
    if (lane < 16) {
        float4 v = xv[768 + lane];
        s0 += v.x + v.y; s1 += v.z + v.w;
    }
    float s = (s0 + s1) + (s2 + s3);
    #pragma unroll
    for (int off = 16; off; off >>= 1)
        s += __shfl_xor_sync(0xffffffffu, s, off);

    float p = s * (1.0f / 3136.0f);          // mean, present in all lanes
    int b = pair >> 8;
    int c = pair & 255;
    if (lane < PFD) {
        float v = fmaf(p, W1[c * PFD + lane], b1[c * PFD + lane]);
        g_concat[b * KDIM + c * PFD + lane] = fmaxf(v, 0.f);
    }
}

// ---------------------------------------------------------------------------
// Kernel 2: h_partial[ks][b][j] = sum_{k in slice ks} concat[b][k] * W2[j][k]
// 128 blocks, [128b x 32j] tile per K-slice of 128. 4x4 register blocking.
// ---------------------------------------------------------------------------
__global__ void __launch_bounds__(256) gemm2_kernel(const float* __restrict__ W2) {
    __shared__ float cs[BATCH * 68];   // concat tile [128][64] (stride 68)
    __shared__ float ws[32 * 68];      // W2 tile     [32][64]  (stride 68)

    int jt = blockIdx.x & 7;           // j-tile
    int ks = blockIdx.x >> 3;          // k-split
    int j0 = jt * 32;
    int t = threadIdx.x;
    int jgrp  = t & 7;                 // j = j0 + jgrp + 8*jjj
    int bbase = t >> 3;                // b = bbase + 32*bi

    float acc[4][4];
    #pragma unroll
    for (int a = 0; a < 4; a++)
        #pragma unroll
        for (int b = 0; b < 4; b++) acc[a][b] = 0.f;

    #pragma unroll
    for (int kt = 0; kt < 2; kt++) {
        int kb = ks * 128 + kt * 64;

        #pragma unroll
        for (int i = 0; i < 8; i++) {
            int f = t + 256 * i;
            int bb = f >> 4, kq = f & 15;
            float4 v = *(const float4*)(g_concat + bb * KDIM + kb + kq * 4);
            *(float4*)(cs + bb * 68 + kq * 4) = v;
        }
        #pragma unroll
        for (int i = 0; i < 2; i++) {
            int f = t + 256 * i;
            int jj = f >> 4, kq = f & 15;
            float4 v = *(const float4*)(W2 + (long)(j0 + jj) * KDIM + kb + kq * 4);
            *(float4*)(ws + jj * 68 + kq * 4) = v;
        }
        __syncthreads();

        #pragma unroll 4
        for (int k = 0; k < 64; k++) {
            float wv[4], cv[4];
            #pragma unroll
            for (int jjj = 0; jjj < 4; jjj++) wv[jjj] = ws[(jgrp + 8 * jjj) * 68 + k];
            #pragma unroll
            for (int bi = 0; bi < 4; bi++)    cv[bi] = cs[(bbase + 32 * bi) * 68 + k];
            #pragma unroll
            for (int jjj = 0; jjj < 4; jjj++)
                #pragma unroll
                for (int bi = 0; bi < 4; bi++)
                    acc[jjj][bi] = fmaf(wv[jjj], cv[bi], acc[jjj][bi]);
        }
        __syncthreads();
    }

    #pragma unroll
    for (int jjj = 0; jjj < 4; jjj++) {
        int j = j0 + jgrp + 8 * jjj;
        #pragma unroll
        for (int bi = 0; bi < 4; bi++) {
            int b = bbase + 32 * bi;
            g_hpart[(ks * BATCH + b) * JH + j] = acc[jjj][bi];
        }
    }
}

// ---------------------------------------------------------------------------
// Kernel 2.5: g_h[b][j] = relu(b2[j] + sum_ks hpart[ks][b][j]).  One pass.
// ---------------------------------------------------------------------------
__global__ void __launch_bounds__(256) reduceh_kernel(const float* __restrict__ b2) {
    int lin = blockIdx.x * 256 + threadIdx.x;   // 32768 elements
    int j = lin & 255;
    float v = b2[j];
    #pragma unroll
    for (int ks = 0; ks < KSPLIT; ks++)
        v += g_hpart[ks * (BATCH * JH) + lin];
    g_h[lin] = fmaxf(v, 0.f);
}

// ---------------------------------------------------------------------------
// Kernel 3 v5: out[b][n] = sum_j g_h[b][j] * W3[n][j] + b3[n]
// Block = [32b x 32n], 512 threads = 16 warps (4/SMSP -> real latency hiding).
// Warp w owns 2 n-rows; lanes span 32 b. h staged once in smem with row
// stride 260 floats (= 4 mod 32): LDS.128 is conflict-free (quarter-warp
// phases tile all 32 banks). Per j4: 2 warp-uniform LDG.128 (W3) +
// 1 LDS.128 (h) + 8 FMA. unroll 4 -> 8 LDGs front-batched (MLP=8 vs the
// cold-W3 DRAM miss). bid nt-major: the 4 b-group blocks sharing an n-tile
// are adjacent -> W3 L2 miss-merge. Grid = 32 nt x 4 bg = 128.
// ---------------------------------------------------------------------------
__global__ void __launch_bounds__(512) gemm3_kernel(const float* __restrict__ W3,
                                                    const float* __restrict__ b3,
                                                    float* __restrict__ out) {
    __shared__ float hs[32 * 260];     // [32b][256j], stride 260 (33.3 KB)

    int nt = blockIdx.x >> 2;          // n-tile 0..31  (nt-major placement)
    int bg = blockIdx.x & 3;           // b-group 0..3
    int b0 = bg * 32;
    int n0 = nt * 32;
    int t = threadIdx.x;
    int lane = t & 31;
    int w = t >> 5;                    // warp 0..15

    // Stage h slice [32b][256j]: 2048 float4, 4 per thread, coalesced.
    #pragma unroll
    for (int i = 0; i < 4; i++) {
        int f = t + 512 * i;           // 0..2047
        int bb = f >> 6;               // 0..31
        int k4 = f & 63;               // j quad 0..63
        float4 v = *(const float4*)(g_h + (b0 + bb) * JH + k4 * 4);
        *(float4*)(hs + bb * 260 + k4 * 4) = v;   // 260*4 and 16 both divide: aligned
    }
    __syncthreads();

    // Warp-uniform W3 row pointers for the 2 owned n-rows.
    int n_a = n0 + w * 2;
    int n_b = n_a + 1;
    bool va = n_a < NCLS, vb = n_b < NCLS;
    const float* wpa = W3 + (long)(va ? n_a : 0) * JH;
    const float* wpb = W3 + (long)(vb ? n_b : 0) * JH;

    float acc0 = 0.f, acc1 = 0.f;
    const float4* hrow = (const float4*)(hs + lane * 260);

    #pragma unroll 4
    for (int j4 = 0; j4 < 64; j4++) {
        float4 wa = *(const float4*)(wpa + j4 * 4);   // warp-uniform broadcast
        float4 wb = *(const float4*)(wpb + j4 * 4);
        float4 h  = hrow[j4];                          // conflict-free LDS.128
        acc0 = fmaf(wa.x, h.x, acc0);
        acc0 = fmaf(wa.y, h.y, acc0);
        acc0 = fmaf(wa.z, h.z, acc0);
        acc0 = fmaf(wa.w, h.w, acc0);
        acc1 = fmaf(wb.x, h.x, acc1);
        acc1 = fmaf(wb.y, h.y, acc1);
        acc1 = fmaf(wb.z, h.z, acc1);
        acc1 = fmaf(wb.w, h.w, acc1);
    }

    if (va) out[(long)(b0 + lane) * NCLS + n_a] = acc0 + b3[n_a];
    if (vb) out[(long)(b0 + lane) * NCLS + n_b] = acc1 + b3[n_b];
}

// ---------------------------------------------------------------------------
extern "C" void kernel_launch(void* const* d_in, const int* in_sizes, int n_in,
                              void* d_out, int out_size) {
    const float* x  = (const float*)d_in[0];
    const float* W1 = (const float*)d_in[1];
    const float* b1 = (const float*)d_in[2];
    const float* W2 = (const float*)d_in[3];
    const float* b2 = (const float*)d_in[4];
    const float* W3 = (const float*)d_in[5];
    const float* b3 = (const float*)d_in[6];
    float* out = (float*)d_out;

    pool_kernel<<<(BATCH * CH) / 16, 512>>>(x, W1, b1);       // 2048 blocks
    gemm2_kernel<<<KSPLIT * JTILES, 256>>>(W2);               // 128 blocks
    reduceh_kernel<<<(BATCH * JH) / 256, 256>>>(b2);          // 128 blocks
    gemm3_kernel<<<128, 512>>>(W3, b3, out);                  // 32 nt x 4 bg
}